// round 13
// baseline (speedup 1.0000x reference)
#include <cuda_runtime.h>

#define HWPX (1024*1024)
#define NB 8
#define NA 8
#define NK 16
#define NSEG 17
#define EPSV 1e-4f
#define GRIDX 128
#define NTILE 1024   // 256-wide float4-tiles per plane: HWPX/4/256 = 1024

// per-block smem constant layout (floats):
// [0,32)    : per-axis float4: {A0*dxi, A1*dxi, A2*dxi, m2}
// [32,64)   : per-axis float4: {pv0, pv1, pv2, 0}
// [64,336)  : tab[a][k] as float2 (dy, c02), 8*17*2 = 272 floats
#define CB_AP   0
#define CB_PV   32
#define CB_TAB  64
#define CB_SIZE (64 + NA*NSEG*2)   // 336 floats

__global__ __launch_bounds__(256, 5)
void spline_persist_kernel(const float* __restrict__ raw,
                           const float* __restrict__ ys,
                           const float* __restrict__ A,
                           float* __restrict__ out) {
    __shared__ __align__(16) float sc[CB_SIZE];
    const int b = blockIdx.y;
    const size_t base = (size_t)b * 3 * HWPX;
    const int tid = threadIdx.x;

    // ---- first tile's loads issued BEFORE the prologue (latency overlap) ----
    const int v0i = blockIdx.x * 256 + tid;
    float4 R  = ((const float4*)(raw + base          ))[v0i];
    float4 G  = ((const float4*)(raw + base +   HWPX ))[v0i];
    float4 Bv = ((const float4*)(raw + base + 2*HWPX ))[v0i];

    // ---- parallel prologue (once per block) ----
    const float* Ab = A + b * 3 * NA;
    if (tid < 24) {
        // pinv element (a,c):  pinv = A^T (A A^T)^-1
        const int a = tid / 3;
        const int c = tid % 3;
        float Am[3][NA];
        #pragma unroll
        for (int i = 0; i < 3; i++)
            #pragma unroll
            for (int j = 0; j < NA; j++)
                Am[i][j] = __ldg(Ab + i * NA + j);

        float M[3][3];
        #pragma unroll
        for (int i = 0; i < 3; i++)
            #pragma unroll
            for (int j = 0; j < 3; j++) {
                float s = 0.f;
                #pragma unroll
                for (int k = 0; k < NA; k++) s += Am[i][k] * Am[j][k];
                M[i][j] = s;
            }
        float c00 = M[1][1]*M[2][2] - M[1][2]*M[2][1];
        float c01 = M[1][2]*M[2][0] - M[1][0]*M[2][2];
        float c02 = M[1][0]*M[2][1] - M[1][1]*M[2][0];
        float det = M[0][0]*c00 + M[0][1]*c01 + M[0][2]*c02;
        float id  = 1.0f / det;
        float invc[3];
        if (c == 0)      { invc[0] = c00*id;
                           invc[1] = c01*id;
                           invc[2] = c02*id; }
        else if (c == 1) { invc[0] = (M[0][2]*M[2][1] - M[0][1]*M[2][2])*id;
                           invc[1] = (M[0][0]*M[2][2] - M[0][2]*M[2][0])*id;
                           invc[2] = (M[0][1]*M[2][0] - M[0][0]*M[2][1])*id; }
        else             { invc[0] = (M[0][1]*M[1][2] - M[0][2]*M[1][1])*id;
                           invc[1] = (M[0][2]*M[1][0] - M[0][0]*M[1][2])*id;
                           invc[2] = (M[0][0]*M[1][1] - M[0][1]*M[1][0])*id; }
        float s = 0.f;
        #pragma unroll
        for (int k = 0; k < 3; k++) s += Am[k][a] * invc[k];
        sc[CB_PV + a * 4 + c] = s;
    } else if (tid >= 32 && tid < 40) {
        const int a = tid - 32;
        float v0 = __ldg(Ab + 0 * NA + a);
        float v1 = __ldg(Ab + 1 * NA + a);
        float v2 = __ldg(Ab + 2 * NA + a);
        float mn = fminf(v0,0.f) + fminf(v1,0.f) + fminf(v2,0.f);
        float mx = fmaxf(v0,0.f) + fmaxf(v1,0.f) + fmaxf(v2,0.f);
        float dx  = (mx + EPSV - mn) / 17.0f;
        float dxi = 1.0f / dx;
        sc[CB_AP + a * 4 + 0] = v0 * dxi;
        sc[CB_AP + a * 4 + 1] = v1 * dxi;
        sc[CB_AP + a * 4 + 2] = v2 * dxi;
        sc[CB_AP + a * 4 + 3] = -mn * dxi;
    } else if (tid >= 56 && tid < 64) {
        sc[CB_PV + (tid - 56) * 4 + 3] = 0.f;   // pv padding
    } else if (tid >= 64 && tid < 64 + NA * NSEG) {
        const int idx = tid - 64;
        const int a = idx / NSEG;
        const int k = idx % NSEG;
        float v0 = __ldg(Ab + 0 * NA + a);
        float v1 = __ldg(Ab + 1 * NA + a);
        float v2 = __ldg(Ab + 2 * NA + a);
        float mn = fminf(v0,0.f) + fminf(v1,0.f) + fminf(v2,0.f);
        float mx = fmaxf(v0,0.f) + fmaxf(v1,0.f) + fmaxf(v2,0.f);
        const float* ysa = ys + (b * NA + a) * NK;
        float ylo = (k == 0)  ? mn : __ldg(ysa + k - 1);
        float yhi = (k == NK) ? mx : __ldg(ysa + k);
        float dy   = yhi - ylo;
        float c02v = yhi - (float)(k + 1) * dy;
        sc[CB_TAB + (a * NSEG + k) * 2 + 0] = dy;
        sc[CB_TAB + (a * NSEG + k) * 2 + 1] = c02v;
    }
    __syncthreads();

    const float4* sap  = (const float4*)(sc + CB_AP);
    const float4* spv  = (const float4*)(sc + CB_PV);
    const float2* stab = (const float2*)(sc + CB_TAB);

    // ---- persistent tile loop, no manual prefetch (concurrency covers latency) ----
    for (int x = blockIdx.x; x < NTILE; x += GRIDX) {
        const int vidx = x * 256 + tid;
        if (x != blockIdx.x) {
            R  = ((const float4*)(raw + base          ))[vidx];
            G  = ((const float4*)(raw + base +   HWPX ))[vidx];
            Bv = ((const float4*)(raw + base + 2*HWPX ))[vidx];
        }

        float rr[4] = {R.x,  R.y,  R.z,  R.w};
        float gg[4] = {G.x,  G.y,  G.z,  G.w};
        float bb[4] = {Bv.x, Bv.y, Bv.z, Bv.w};

        float a0[4], a1[4], a2[4];
        #pragma unroll
        for (int q = 0; q < 4; q++) { a0[q] = 0.f; a1[q] = 0.f; a2[q] = 0.f; }

        #pragma unroll
        for (int a = 0; a < NA; a++) {
            const float4 ap = sap[a];
            const float4 pv = spv[a];
            const float2* atab = stab + a * NSEG;
            #pragma unroll
            for (int q = 0; q < 4; q++) {
                // u in [0,17) by construction (EPS margin >> roundoff)
                float u = fmaf(rr[q], ap.x, fmaf(gg[q], ap.y, fmaf(bb[q], ap.z, ap.w)));
                int   k = (int)u;
                float2 tc = atab[k];
                float est = fmaf(u, tc.x, tc.y);
                a0[q] = fmaf(est, pv.x, a0[q]);
                a1[q] = fmaf(est, pv.y, a1[q]);
                a2[q] = fmaf(est, pv.z, a2[q]);
            }
        }

        ((float4*)(out + base          ))[vidx] = make_float4(a0[0], a0[1], a0[2], a0[3]);
        ((float4*)(out + base +   HWPX ))[vidx] = make_float4(a1[0], a1[1], a1[2], a1[3]);
        ((float4*)(out + base + 2*HWPX ))[vidx] = make_float4(a2[0], a2[1], a2[2], a2[3]);
    }
}

extern "C" void kernel_launch(void* const* d_in, const int* in_sizes, int n_in,
                              void* d_out, int out_size) {
    const float* raw = (const float*)d_in[0];
    const float* ys  = (const float*)d_in[1];
    const float* A   = (const float*)d_in[2];
    float* out = (float*)d_out;

    dim3 grid(GRIDX, NB);
    spline_persist_kernel<<<grid, 256>>>(raw, ys, A, out);
}

// round 14
// speedup vs baseline: 1.1420x; 1.1420x over previous
#include <cuda_runtime.h>

#define HWPX (1024*1024)
#define NB 8
#define NA 8
#define NK 16
#define NSEG 17
#define EPSV 1e-4f

// per-block smem constant layout (floats):
// [0,32)    : per-axis float4: {A0*dxi, A1*dxi, A2*dxi, m2}
// [32,64)   : per-axis float4: {pv0, pv1, pv2, 0}
// [64,336)  : tab[a][k] as float2 (dy, c02), 8*17*2 = 272 floats
#define CB_AP   0
#define CB_PV   32
#define CB_TAB  64
#define CB_SIZE (64 + NA*NSEG*2)   // 336 floats

__global__ __launch_bounds__(256, 5)
void spline_fused_kernel(const float* __restrict__ raw,
                         const float* __restrict__ ys,
                         const float* __restrict__ A,
                         float* __restrict__ out) {
    __shared__ __align__(16) float sc[CB_SIZE];
    __shared__ __align__(16) float stg[24 + NA * NK];   // staged A (24) + ys (128)
    const int b = blockIdx.y;
    const size_t base = (size_t)b * 3 * HWPX;
    const int tid = threadIdx.x;
    const int vidx = blockIdx.x * 256 + tid;   // float4 index within plane

    // ---- big independent global loads FIRST (latency overlaps prologue) ----
    float4 R  = ((const float4*)(raw + base          ))[vidx];
    float4 G  = ((const float4*)(raw + base +   HWPX ))[vidx];
    float4 Bv = ((const float4*)(raw + base + 2*HWPX ))[vidx];

    // ---- stage 1: vectorized staging of A (6xfloat4) + ys (32xfloat4) ----
    if (tid < 6) {
        ((float4*)stg)[tid] = ((const float4*)(A + b * 3 * NA))[tid];
    } else if (tid < 38) {
        ((float4*)(stg + 24))[tid - 6] = ((const float4*)(ys + b * NA * NK))[tid - 6];
    }
    __syncthreads();

    const float* sA  = stg;        // A[c*8+a]
    const float* sys = stg + 24;   // ys[a*16+k]

    // ---- stage 2: parallel constant build, all reads from smem ----
    if (tid < 24) {
        // pinv element (a,c):  pinv = A^T (A A^T)^-1
        const int a = tid / 3;
        const int c = tid % 3;
        float Am[3][NA];
        #pragma unroll
        for (int i = 0; i < 3; i++)
            #pragma unroll
            for (int j = 0; j < NA; j++)
                Am[i][j] = sA[i * NA + j];

        float M[3][3];
        #pragma unroll
        for (int i = 0; i < 3; i++)
            #pragma unroll
            for (int j = 0; j < 3; j++) {
                float s = 0.f;
                #pragma unroll
                for (int k = 0; k < NA; k++) s += Am[i][k] * Am[j][k];
                M[i][j] = s;
            }
        float c00 = M[1][1]*M[2][2] - M[1][2]*M[2][1];
        float c01 = M[1][2]*M[2][0] - M[1][0]*M[2][2];
        float c02 = M[1][0]*M[2][1] - M[1][1]*M[2][0];
        float det = M[0][0]*c00 + M[0][1]*c01 + M[0][2]*c02;
        float id  = 1.0f / det;
        float invc[3];
        if (c == 0)      { invc[0] = c00*id;
                           invc[1] = c01*id;
                           invc[2] = c02*id; }
        else if (c == 1) { invc[0] = (M[0][2]*M[2][1] - M[0][1]*M[2][2])*id;
                           invc[1] = (M[0][0]*M[2][2] - M[0][2]*M[2][0])*id;
                           invc[2] = (M[0][1]*M[2][0] - M[0][0]*M[2][1])*id; }
        else             { invc[0] = (M[0][1]*M[1][2] - M[0][2]*M[1][1])*id;
                           invc[1] = (M[0][2]*M[1][0] - M[0][0]*M[1][2])*id;
                           invc[2] = (M[0][0]*M[1][1] - M[0][1]*M[1][0])*id; }
        float s = 0.f;
        #pragma unroll
        for (int k = 0; k < 3; k++) s += Am[k][a] * invc[k];
        sc[CB_PV + a * 4 + c] = s;
    } else if (tid >= 32 && tid < 40) {
        const int a = tid - 32;
        float v0 = sA[0 * NA + a];
        float v1 = sA[1 * NA + a];
        float v2 = sA[2 * NA + a];
        float mn = fminf(v0,0.f) + fminf(v1,0.f) + fminf(v2,0.f);
        float mx = fmaxf(v0,0.f) + fmaxf(v1,0.f) + fmaxf(v2,0.f);
        float dx  = (mx + EPSV - mn) / 17.0f;
        float dxi = 1.0f / dx;
        sc[CB_AP + a * 4 + 0] = v0 * dxi;
        sc[CB_AP + a * 4 + 1] = v1 * dxi;
        sc[CB_AP + a * 4 + 2] = v2 * dxi;
        sc[CB_AP + a * 4 + 3] = -mn * dxi;
    } else if (tid >= 56 && tid < 64) {
        sc[CB_PV + (tid - 56) * 4 + 3] = 0.f;   // pv padding
    } else if (tid >= 64 && tid < 64 + NA * NSEG) {
        const int idx = tid - 64;
        const int a = idx / NSEG;
        const int k = idx % NSEG;
        float v0 = sA[0 * NA + a];
        float v1 = sA[1 * NA + a];
        float v2 = sA[2 * NA + a];
        float mn = fminf(v0,0.f) + fminf(v1,0.f) + fminf(v2,0.f);
        float mx = fmaxf(v0,0.f) + fmaxf(v1,0.f) + fmaxf(v2,0.f);
        float ylo = (k == 0)  ? mn : sys[a * NK + k - 1];
        float yhi = (k == NK) ? mx : sys[a * NK + k];
        float dy   = yhi - ylo;
        float c02v = yhi - (float)(k + 1) * dy;
        sc[CB_TAB + (a * NSEG + k) * 2 + 0] = dy;
        sc[CB_TAB + (a * NSEG + k) * 2 + 1] = c02v;
    }
    __syncthreads();

    // ---- main loop (identical to R10) ----
    const float4* sap  = (const float4*)(sc + CB_AP);
    const float4* spv  = (const float4*)(sc + CB_PV);
    const float2* stab = (const float2*)(sc + CB_TAB);

    float rr[4] = {R.x,  R.y,  R.z,  R.w};
    float gg[4] = {G.x,  G.y,  G.z,  G.w};
    float bb[4] = {Bv.x, Bv.y, Bv.z, Bv.w};

    float a0[4], a1[4], a2[4];
    #pragma unroll
    for (int q = 0; q < 4; q++) { a0[q] = 0.f; a1[q] = 0.f; a2[q] = 0.f; }

    #pragma unroll
    for (int a = 0; a < NA; a++) {
        const float4 ap = sap[a];
        const float4 pv = spv[a];
        const float2* atab = stab + a * NSEG;
        #pragma unroll
        for (int q = 0; q < 4; q++) {
            // u in [0,17) by construction (EPS margin >> roundoff); trunc handles -eps
            float u = fmaf(rr[q], ap.x, fmaf(gg[q], ap.y, fmaf(bb[q], ap.z, ap.w)));
            int   k = (int)u;
            float2 tc = atab[k];
            float est = fmaf(u, tc.x, tc.y);
            a0[q] = fmaf(est, pv.x, a0[q]);
            a1[q] = fmaf(est, pv.y, a1[q]);
            a2[q] = fmaf(est, pv.z, a2[q]);
        }
    }

    ((float4*)(out + base          ))[vidx] = make_float4(a0[0], a0[1], a0[2], a0[3]);
    ((float4*)(out + base +   HWPX ))[vidx] = make_float4(a1[0], a1[1], a1[2], a1[3]);
    ((float4*)(out + base + 2*HWPX ))[vidx] = make_float4(a2[0], a2[1], a2[2], a2[3]);
}

extern "C" void kernel_launch(void* const* d_in, const int* in_sizes, int n_in,
                              void* d_out, int out_size) {
    const float* raw = (const float*)d_in[0];
    const float* ys  = (const float*)d_in[1];
    const float* A   = (const float*)d_in[2];
    float* out = (float*)d_out;

    dim3 grid(HWPX / (256 * 4), NB);
    spline_fused_kernel<<<grid, 256>>>(raw, ys, A, out);
}

// round 15
// speedup vs baseline: 1.2355x; 1.0819x over previous
#include <cuda_runtime.h>

#define HWPX (1024*1024)
#define NB 8
#define NA 8
#define NK 16
#define NSEG 17
#define EPSV 1e-4f

// per-block smem constant layout (floats):
// [0,32)    : per-axis float4: {A0*dxi, A1*dxi, A2*dxi, m2}
// [32,64)   : per-axis float4: {pv0, pv1, pv2, 0}
// [64,336)  : tab[a][k] as float2 (dy, c02), 8*17*2 = 272 floats
#define CB_AP   0
#define CB_PV   32
#define CB_TAB  64
#define CB_SIZE (64 + NA*NSEG*2)   // 336 floats

__global__ __launch_bounds__(256, 6)
void spline_fused_kernel(const float* __restrict__ raw,
                        const float* __restrict__ ys,
                        const float* __restrict__ A,
                        float* __restrict__ out) {
    __shared__ __align__(16) float sc[CB_SIZE];
    const int b = blockIdx.y;
    const size_t base = (size_t)b * 3 * HWPX;
    const int vidx = blockIdx.x * 256 + threadIdx.x;   // float4 index within plane

    // ---- issue the big independent global loads FIRST (latency overlaps prologue)
    float4 R  = ((const float4*)(raw + base          ))[vidx];
    float4 G  = ((const float4*)(raw + base +   HWPX ))[vidx];
    float4 Bv = ((const float4*)(raw + base + 2*HWPX ))[vidx];

    // ---- parallel prologue: redundant per-block, spread over ~170 threads ----
    const int t = threadIdx.x;
    const float* Ab = A + b * 3 * NA;

    if (t < 24) {
        // pinv element (a,c):  pinv = A^T (A A^T)^-1
        const int a = t / 3;
        const int c = t % 3;
        float Am[3][NA];
        #pragma unroll
        for (int i = 0; i < 3; i++)
            #pragma unroll
            for (int j = 0; j < NA; j++)
                Am[i][j] = __ldg(Ab + i * NA + j);

        float M[3][3];
        #pragma unroll
        for (int i = 0; i < 3; i++)
            #pragma unroll
            for (int j = 0; j < 3; j++) {
                float s = 0.f;
                #pragma unroll
                for (int k = 0; k < NA; k++) s += Am[i][k] * Am[j][k];
                M[i][j] = s;
            }
        float c00 = M[1][1]*M[2][2] - M[1][2]*M[2][1];
        float c01 = M[1][2]*M[2][0] - M[1][0]*M[2][2];
        float c02 = M[1][0]*M[2][1] - M[1][1]*M[2][0];
        float det = M[0][0]*c00 + M[0][1]*c01 + M[0][2]*c02;
        float id  = 1.0f / det;
        float invc[3];
        if (c == 0)      { invc[0] = c00*id;
                           invc[1] = c01*id;
                           invc[2] = c02*id; }
        else if (c == 1) { invc[0] = (M[0][2]*M[2][1] - M[0][1]*M[2][2])*id;
                           invc[1] = (M[0][0]*M[2][2] - M[0][2]*M[2][0])*id;
                           invc[2] = (M[0][1]*M[2][0] - M[0][0]*M[2][1])*id; }
        else             { invc[0] = (M[0][1]*M[1][2] - M[0][2]*M[1][1])*id;
                           invc[1] = (M[0][2]*M[1][0] - M[0][0]*M[1][2])*id;
                           invc[2] = (M[0][0]*M[1][1] - M[0][1]*M[1][0])*id; }
        float s = 0.f;
        #pragma unroll
        for (int k = 0; k < 3; k++) s += Am[k][a] * invc[k];
        sc[CB_PV + a * 4 + c] = s;
    } else if (t >= 32 && t < 40) {
        const int a = t - 32;
        float v0 = __ldg(Ab + 0 * NA + a);
        float v1 = __ldg(Ab + 1 * NA + a);
        float v2 = __ldg(Ab + 2 * NA + a);
        float mn = fminf(v0,0.f) + fminf(v1,0.f) + fminf(v2,0.f);
        float mx = fmaxf(v0,0.f) + fmaxf(v1,0.f) + fmaxf(v2,0.f);
        float dx  = (mx + EPSV - mn) / 17.0f;
        float dxi = 1.0f / dx;
        sc[CB_AP + a * 4 + 0] = v0 * dxi;
        sc[CB_AP + a * 4 + 1] = v1 * dxi;
        sc[CB_AP + a * 4 + 2] = v2 * dxi;
        sc[CB_AP + a * 4 + 3] = -mn * dxi;
    } else if (t >= 56 && t < 64) {
        sc[CB_PV + (t - 56) * 4 + 3] = 0.f;   // pv padding
    } else if (t >= 64 && t < 64 + NA * NSEG) {
        const int idx = t - 64;
        const int a = idx / NSEG;
        const int k = idx % NSEG;
        float v0 = __ldg(Ab + 0 * NA + a);
        float v1 = __ldg(Ab + 1 * NA + a);
        float v2 = __ldg(Ab + 2 * NA + a);
        float mn = fminf(v0,0.f) + fminf(v1,0.f) + fminf(v2,0.f);
        float mx = fmaxf(v0,0.f) + fmaxf(v1,0.f) + fmaxf(v2,0.f);
        const float* ysa = ys + (b * NA + a) * NK;
        float ylo = (k == 0)  ? mn : __ldg(ysa + k - 1);
        float yhi = (k == NK) ? mx : __ldg(ysa + k);
        float dy   = yhi - ylo;
        float c02v = yhi - (float)(k + 1) * dy;
        sc[CB_TAB + (a * NSEG + k) * 2 + 0] = dy;
        sc[CB_TAB + (a * NSEG + k) * 2 + 1] = c02v;
    }
    __syncthreads();

    // ---- main loop (identical to R10) ----
    const float4* sap  = (const float4*)(sc + CB_AP);
    const float4* spv  = (const float4*)(sc + CB_PV);
    const float2* stab = (const float2*)(sc + CB_TAB);

    float rr[4] = {R.x,  R.y,  R.z,  R.w};
    float gg[4] = {G.x,  G.y,  G.z,  G.w};
    float bb[4] = {Bv.x, Bv.y, Bv.z, Bv.w};

    float a0[4], a1[4], a2[4];
    #pragma unroll
    for (int q = 0; q < 4; q++) { a0[q] = 0.f; a1[q] = 0.f; a2[q] = 0.f; }

    #pragma unroll
    for (int a = 0; a < NA; a++) {
        const float4 ap = sap[a];
        const float4 pv = spv[a];
        const float2* atab = stab + a * NSEG;
        #pragma unroll
        for (int q = 0; q < 4; q++) {
            // u in [0,17) by construction (EPS margin >> roundoff); trunc handles -eps
            float u = fmaf(rr[q], ap.x, fmaf(gg[q], ap.y, fmaf(bb[q], ap.z, ap.w)));
            int   k = (int)u;
            float2 tc = atab[k];
            float est = fmaf(u, tc.x, tc.y);
            a0[q] = fmaf(est, pv.x, a0[q]);
            a1[q] = fmaf(est, pv.y, a1[q]);
            a2[q] = fmaf(est, pv.z, a2[q]);
        }
    }

    ((float4*)(out + base          ))[vidx] = make_float4(a0[0], a0[1], a0[2], a0[3]);
    ((float4*)(out + base +   HWPX ))[vidx] = make_float4(a1[0], a1[1], a1[2], a1[3]);
    ((float4*)(out + base + 2*HWPX ))[vidx] = make_float4(a2[0], a2[1], a2[2], a2[3]);
}

extern "C" void kernel_launch(void* const* d_in, const int* in_sizes, int n_in,
                              void* d_out, int out_size) {
    const float* raw = (const float*)d_in[0];
    const float* ys  = (const float*)d_in[1];
    const float* A   = (const float*)d_in[2];
    float* out = (float*)d_out;

    dim3 grid(HWPX / (256 * 4), NB);
    spline_fused_kernel<<<grid, 256>>>(raw, ys, A, out);
}